// round 2
// baseline (speedup 1.0000x reference)
#include <cuda_runtime.h>
#include <stdint.h>

#define D 128
#define MAX_N (1 << 18)   // 262144 >= 100000 segments, static scratch

__device__ float g_counts[MAX_N];

// ---------------------------------------------------------------------------
// Kernel 1: zero output and counts
// ---------------------------------------------------------------------------
__global__ void zero_kernel(float4* __restrict__ out4, long long n4, int N) {
    long long i = (long long)blockIdx.x * blockDim.x + threadIdx.x;
    long long stride = (long long)gridDim.x * blockDim.x;
    for (long long k = i; k < n4; k += stride)
        out4[k] = make_float4(0.f, 0.f, 0.f, 0.f);
    for (long long k = i; k < N; k += stride)
        g_counts[k] = 0.f;
}

// ---------------------------------------------------------------------------
// Kernel 2: one warp per edge; vector reduction into output, count per edge
// ---------------------------------------------------------------------------
__global__ void edge_kernel(const float4* __restrict__ msg4,
                            const int* __restrict__ index,   // int32 (JAX x64 off)
                            float* __restrict__ out,
                            int E) {
    int gtid = blockIdx.x * blockDim.x + threadIdx.x;
    int edge = gtid >> 5;
    int lane = gtid & 31;
    if (edge >= E) return;

    int seg = __ldg(&index[edge]);
    float4 v = __ldg(&msg4[(long long)edge * (D / 4) + lane]);

    float* dst = out + (long long)seg * D + lane * 4;
    asm volatile("red.global.add.v4.f32 [%0], {%1,%2,%3,%4};"
                 :: "l"(dst), "f"(v.x), "f"(v.y), "f"(v.z), "f"(v.w)
                 : "memory");

    if (lane == 0)
        atomicAdd(&g_counts[seg], 1.0f);
}

// ---------------------------------------------------------------------------
// Kernel 3: divide sums by max(count, 1)
// ---------------------------------------------------------------------------
__global__ void divide_kernel(float4* __restrict__ out4, int N) {
    long long i = (long long)blockIdx.x * blockDim.x + threadIdx.x;
    long long total = (long long)N * (D / 4);
    if (i >= total) return;
    int row = (int)(i >> 5);           // D/4 == 32
    float c = g_counts[row];
    float inv = 1.0f / fmaxf(c, 1.0f);
    float4 v = out4[i];
    v.x *= inv; v.y *= inv; v.z *= inv; v.w *= inv;
    out4[i] = v;
}

// ---------------------------------------------------------------------------
extern "C" void kernel_launch(void* const* d_in, const int* in_sizes, int n_in,
                              void* d_out, int out_size) {
    const float4* msg4  = (const float4*)d_in[0];
    const int*    index = (const int*)d_in[1];
    // d_in[2] (t) unused by the reference; d_in[3] (dim_size) derived from out_size
    float* out = (float*)d_out;

    int E = in_sizes[1];           // number of edges
    int N = out_size / D;          // number of segments

    long long n4 = (long long)out_size / 4;

    {   // zero
        zero_kernel<<<2048, 256>>>((float4*)out, n4, N);
    }
    {   // scatter-add: one warp per edge
        int threads = 256;
        long long total_threads = (long long)E * 32;
        int blocks = (int)((total_threads + threads - 1) / threads);
        edge_kernel<<<blocks, threads>>>(msg4, index, out, E);
    }
    {   // divide
        int threads = 256;
        long long total = (long long)N * (D / 4);
        int blocks = (int)((total + threads - 1) / threads);
        divide_kernel<<<blocks, threads>>>((float4*)out, N);
    }
}

// round 3
// speedup vs baseline: 1.0389x; 1.0389x over previous
#include <cuda_runtime.h>
#include <stdint.h>

#define D 128
#define MAX_N (1 << 18)   // 262144 >= 100000 segments, static scratch
#define EPW 4             // edges per warp

__device__ float g_counts[MAX_N];

// ---------------------------------------------------------------------------
// Kernel 1: zero output and counts
// ---------------------------------------------------------------------------
__global__ void zero_kernel(float4* __restrict__ out4, long long n4, int N) {
    long long i = (long long)blockIdx.x * blockDim.x + threadIdx.x;
    long long stride = (long long)gridDim.x * blockDim.x;
    for (long long k = i; k < n4; k += stride)
        out4[k] = make_float4(0.f, 0.f, 0.f, 0.f);
    for (long long k = i; k < N; k += stride)
        g_counts[k] = 0.f;
}

// ---------------------------------------------------------------------------
// Kernel 2: 4 edges per warp; front-batched loads, vector reductions
// ---------------------------------------------------------------------------
__global__ __launch_bounds__(256) void edge_kernel(
        const float4* __restrict__ msg4,
        const int* __restrict__ index,   // int32 (JAX x64 off)
        float* __restrict__ out,
        int E) {
    int warp_id = (blockIdx.x * blockDim.x + threadIdx.x) >> 5;
    int lane = threadIdx.x & 31;
    long long base = (long long)warp_id * EPW;
    if (base >= E) return;

    // one coalesced index load: lanes 0..EPW-1 fetch the 4 segment ids
    int seg_l = 0;
    if (lane < EPW && base + lane < E)
        seg_l = __ldg(&index[base + lane]);

    // front-batch the 4 independent 512B row loads (MLP_p1 = 4)
    float4 v[EPW];
#pragma unroll
    for (int e = 0; e < EPW; e++) {
        if (base + e < E)
            v[e] = __ldg(&msg4[(base + e) * (D / 4) + lane]);
    }

#pragma unroll
    for (int e = 0; e < EPW; e++) {
        if (base + e >= E) break;
        int seg = __shfl_sync(0xffffffffu, seg_l, e);
        float* dst = out + (long long)seg * D + lane * 4;
        asm volatile("red.global.add.v4.f32 [%0], {%1,%2,%3,%4};"
                     :: "l"(dst), "f"(v[e].x), "f"(v[e].y), "f"(v[e].z), "f"(v[e].w)
                     : "memory");
        if (lane == e)   // spread count atomics across 4 lanes, issued in parallel
            atomicAdd(&g_counts[seg], 1.0f);
    }
}

// ---------------------------------------------------------------------------
// Kernel 3: divide sums by max(count, 1)
// ---------------------------------------------------------------------------
__global__ void divide_kernel(float4* __restrict__ out4, int N) {
    long long i = (long long)blockIdx.x * blockDim.x + threadIdx.x;
    long long total = (long long)N * (D / 4);
    if (i >= total) return;
    int row = (int)(i >> 5);           // D/4 == 32
    float c = g_counts[row];
    float inv = 1.0f / fmaxf(c, 1.0f);
    float4 v = out4[i];
    v.x *= inv; v.y *= inv; v.z *= inv; v.w *= inv;
    out4[i] = v;
}

// ---------------------------------------------------------------------------
extern "C" void kernel_launch(void* const* d_in, const int* in_sizes, int n_in,
                              void* d_out, int out_size) {
    const float4* msg4  = (const float4*)d_in[0];
    const int*    index = (const int*)d_in[1];
    // d_in[2] (t) unused by the reference
    float* out = (float*)d_out;

    int E = in_sizes[1];           // number of edges
    int N = out_size / D;          // number of segments

    long long n4 = (long long)out_size / 4;

    {   // zero
        zero_kernel<<<2048, 256>>>((float4*)out, n4, N);
    }
    {   // scatter-add: 4 edges per warp
        int threads = 256;
        long long warps = ((long long)E + EPW - 1) / EPW;
        long long total_threads = warps * 32;
        int blocks = (int)((total_threads + threads - 1) / threads);
        edge_kernel<<<blocks, threads>>>(msg4, index, out, E);
    }
    {   // divide
        int threads = 256;
        long long total = (long long)N * (D / 4);
        int blocks = (int)((total + threads - 1) / threads);
        divide_kernel<<<blocks, threads>>>((float4*)out, N);
    }
}